// round 3
// baseline (speedup 1.0000x reference)
#include <cuda_runtime.h>
#include <cuda_fp16.h>
#include <cstddef>

#define TSEQ 512
#define BATCH 128
#define HDIM 1024
#define NZ 4096
#define VOC 128
#define EDIM 256

// ---------------- static device buffers (allocations are forbidden) ----------------
__device__ half  d_U16[(size_t)NZ * HDIM];            // U^T in fp16: [n][k], 8 MB
__device__ float d_embW[VOC * NZ];                    // emb@W + b  : [v][n], 2 MB
__device__ half  d_Ahi[2][BATCH * HDIM];              // ping-pong h_hi (fp16)
__device__ half  d_Alo[2][BATCH * HDIM];              // ping-pong h_lo (fp16 residual)
__device__ float d_c[BATCH * HDIM];
__device__ float d_h[BATCH * HDIM];
__device__ float d_S[(size_t)BATCH * TSEQ * HDIM];    // fp32 states, 256 MB

// ---------------- PTX helpers ----------------
__device__ __forceinline__ unsigned smaddr(const void* p) {
    return (unsigned)__cvta_generic_to_shared(p);
}
__device__ __forceinline__ void cpa16(void* dst, const void* src) {
    asm volatile("cp.async.cg.shared.global [%0], [%1], 16;\n"
                 :: "r"(smaddr(dst)), "l"(src));
}
__device__ __forceinline__ void ldsm_x4(unsigned* r, const void* p) {
    unsigned a = smaddr(p);
    asm volatile("ldmatrix.sync.aligned.m8n8.x4.shared.b16 {%0,%1,%2,%3}, [%4];\n"
                 : "=r"(r[0]), "=r"(r[1]), "=r"(r[2]), "=r"(r[3]) : "r"(a));
}
__device__ __forceinline__ void ldsm_x2(unsigned* r, const void* p) {
    unsigned a = smaddr(p);
    asm volatile("ldmatrix.sync.aligned.m8n8.x2.shared.b16 {%0,%1}, [%2];\n"
                 : "=r"(r[0]), "=r"(r[1]) : "r"(a));
}
__device__ __forceinline__ void mma16816(float* d, const unsigned* a, const unsigned* b) {
    asm volatile("mma.sync.aligned.m16n8k16.row.col.f32.f16.f16.f32 "
                 "{%0,%1,%2,%3},{%4,%5,%6,%7},{%8,%9},{%0,%1,%2,%3};\n"
                 : "+f"(d[0]), "+f"(d[1]), "+f"(d[2]), "+f"(d[3])
                 : "r"(a[0]), "r"(a[1]), "r"(a[2]), "r"(a[3]),
                   "r"(b[0]), "r"(b[1]));
}
__device__ __forceinline__ float sigmoidf_acc(float x) {
    return 1.0f / (1.0f + expf(-x));
}

// ---------------- prep: embW = emb @ W + b   (128 x 4096, K=256) ----------------
__global__ void __launch_bounds__(256) prep_embW(const float* __restrict__ emb,
                                                 const float* __restrict__ W,
                                                 const float* __restrict__ bias) {
    __shared__ float Ws[EDIM][32];                    // 32 KB
    const int n0 = blockIdx.x * 32;                   // grid 128
    for (int i = threadIdx.x; i < EDIM * 32; i += 256) {
        int e = i >> 5, c = i & 31;
        Ws[e][c] = W[(size_t)e * NZ + n0 + c];
    }
    __syncthreads();
    const int c = threadIdx.x & 31;
    for (int v = threadIdx.x >> 5; v < VOC; v += 8) {
        float a = bias[n0 + c];
        const float* er = emb + v * EDIM;
        #pragma unroll 8
        for (int e = 0; e < EDIM; e++) a += er[e] * Ws[e][c];
        d_embW[v * NZ + n0 + c] = a;
    }
}

// ---------------- prep: U fp32 [k][n]  ->  d_U16 fp16 [n][k] ----------------
__global__ void __launch_bounds__(256) prep_U(const float* __restrict__ U) {
    __shared__ float tile[32][33];
    const int n0 = blockIdx.x * 32;                   // gridDim.x = 128
    const int k0 = blockIdx.y * 32;                   // gridDim.y = 32
    const int tx = threadIdx.x & 31, ty = threadIdx.x >> 5;
    #pragma unroll
    for (int i = 0; i < 4; i++) {
        int r = ty + i * 8;
        tile[r][tx] = U[(size_t)(k0 + r) * NZ + n0 + tx];
    }
    __syncthreads();
    #pragma unroll
    for (int i = 0; i < 4; i++) {
        int r = ty + i * 8;
        d_U16[(size_t)(n0 + r) * HDIM + k0 + tx] = __float2half_rn(tile[tx][r]);
    }
}

// ---------------- zero-init state (must run every launch for determinism) ----------------
__global__ void init_state() {
    int i = blockIdx.x * blockDim.x + threadIdx.x;
    if (i < BATCH * HDIM) {
        d_c[i] = 0.f;
        d_h[i] = 0.f;
        d_Ahi[0][i] = __float2half_rn(0.f);
        d_Alo[0][i] = __float2half_rn(0.f);
    }
}

// ---------------- one LSTM step ----------------
// Block bn owns h columns [8bn, 8bn+8) => z columns {g*1024 + 8bn + j}.
// C[128x32] = [h_hi|h_lo][128x1024] @ U16cols[1024x32], 2 fp16 passes sharing B.
struct SPipe {
    half A[2][2][128][40];   // [stage][pass hi/lo][row][32 k + pad8]  40960 B
    half B[2][32][40];       //                      [stage][ci][k]     5120 B
};
#define SMBYTES 46080

__global__ void __launch_bounds__(256) lstm_step(const int* __restrict__ tokens, int t) {
    __shared__ __align__(16) char smraw[SMBYTES];
    SPipe& sp = *reinterpret_cast<SPipe*>(smraw);
    float (*zb)[40] = reinterpret_cast<float(*)[40]>(smraw);   // 20480 B, reused after GEMM

    const int tid  = threadIdx.x;
    const int bn   = blockIdx.x;
    const int rb   = t & 1, wb = rb ^ 1;
    const int lane = tid & 31, wid = tid >> 5;
    const int wm   = wid & 3;     // 4 warps x 32 rows
    const int wn   = wid >> 2;    // 2 warps x 16 cols

    const half* __restrict__ Ahi = d_Ahi[rb];
    const half* __restrict__ Alo = d_Alo[rb];

    float acc[2][2][4];
    #pragma unroll
    for (int i = 0; i < 2; i++)
        #pragma unroll
        for (int j = 0; j < 2; j++)
            #pragma unroll
            for (int e = 0; e < 4; e++) acc[i][j][e] = 0.f;

    // ldmatrix lane addressing (verified against PTX ISA fragment layouts)
    const int aRow = wm * 32 + (lane & 7) + ((lane >> 3) & 1) * 8;
    const int aCol = ((lane >> 4) & 1) * 8;
    const int bRow = wn * 16 + (lane & 7);
    const int bCol = ((lane >> 3) & 1) * 8;

    // one stage = 32 k-values: A hi 512 + A lo 512 + B 128 = 1152 x 16B cp.async
    auto load_stage = [&](int s, int ch) {
        const int k0 = ch * 32;
        for (int i = tid; i < 1152; i += 256) {
            if (i < 1024) {
                int pass = i >> 9, r = (i >> 2) & 127, seg = i & 3;
                const half* src = (pass ? Alo : Ahi) + r * HDIM + k0 + seg * 8;
                cpa16(&sp.A[s][pass][r][seg * 8], src);
            } else {
                int j = i - 1024, ci = j >> 2, seg = j & 3;
                int gcol = (ci >> 3) * HDIM + bn * 8 + (ci & 7);
                cpa16(&sp.B[s][ci][seg * 8],
                      d_U16 + (size_t)gcol * HDIM + k0 + seg * 8);
            }
        }
        asm volatile("cp.async.commit_group;\n");
    };

    load_stage(0, 0);

    for (int ch = 0; ch < 32; ch++) {
        const int cur = ch & 1;
        if (ch < 31) {
            load_stage(cur ^ 1, ch + 1);
            asm volatile("cp.async.wait_group 1;\n");
        } else {
            asm volatile("cp.async.wait_group 0;\n");
        }
        __syncthreads();

        #pragma unroll
        for (int ks = 0; ks < 2; ks++) {
            unsigned bf0[2], bf1[2];
            ldsm_x2(bf0, &sp.B[cur][bRow    ][bCol + ks * 16]);
            ldsm_x2(bf1, &sp.B[cur][bRow + 8][bCol + ks * 16]);
            #pragma unroll
            for (int pass = 0; pass < 2; pass++) {
                unsigned af0[4], af1[4];
                ldsm_x4(af0, &sp.A[cur][pass][aRow     ][aCol + ks * 16]);
                ldsm_x4(af1, &sp.A[cur][pass][aRow + 16][aCol + ks * 16]);
                mma16816(acc[0][0], af0, bf0);
                mma16816(acc[0][1], af0, bf1);
                mma16816(acc[1][0], af1, bf0);
                mma16816(acc[1][1], af1, bf1);
            }
        }
        __syncthreads();
    }

    // ---- spill C to smem ----
    #pragma unroll
    for (int ti = 0; ti < 2; ti++)
        #pragma unroll
        for (int tj = 0; tj < 2; tj++)
            #pragma unroll
            for (int e = 0; e < 4; e++) {
                int r = wm * 32 + ti * 16 + (lane >> 2) + (e >> 1) * 8;
                int c = wn * 16 + tj * 8 + (lane & 3) * 2 + (e & 1);
                zb[r][c] = acc[ti][tj][e];
            }
    __syncthreads();

    // ---- block-local gate + state update: 128 rows x 8 h-cols ----
    for (int e = tid; e < 1024; e += 256) {
        const int bb  = e >> 3, j = e & 7;
        const int col = bn * 8 + j;
        const int tok = tokens[bb * TSEQ + t];
        const float* ew = d_embW + (size_t)tok * NZ + col;

        float zi = zb[bb][j]      + ew[0];
        float zf = zb[bb][8 + j]  + ew[HDIM];
        float zg = zb[bb][16 + j] + ew[2 * HDIM];
        float zo = zb[bb][24 + j] + ew[3 * HDIM];

        float ig = sigmoidf_acc(zi);
        float fg = sigmoidf_acc(zf);
        float gg = tanhf(zg);
        float og = sigmoidf_acc(zo);

        const int si = bb * HDIM + col;
        float cp = d_c[si];
        float cn = fg * cp + ig * gg;
        float hn = og * tanhf(cn);

        bool msk = (tok != 0);
        float ho = msk ? hn : d_h[si];
        float co = msk ? cn : cp;

        d_c[si] = co;
        d_h[si] = ho;
        d_S[((size_t)bb * TSEQ + t) * HDIM + col] = ho;

        half hi = __float2half_rn(ho);
        d_Ahi[wb][si] = hi;
        d_Alo[wb][si] = __float2half_rn(ho - __half2float(hi));
    }
}

// ---------------- decode + softmax: out[row][v] = softmax(S[row]@Wd + bd) ----------------
// 1024 blocks x 64 rows; 4 threads per row, 32 cols each.
__global__ void __launch_bounds__(256) decode_kernel(const float* __restrict__ Wd,
                                                     const float* __restrict__ bd,
                                                     float* __restrict__ out) {
    __shared__ float s[64][33];        // 8448 B
    __shared__ float w[32][128];       // 16384 B
    const int row0 = blockIdx.x * 64;
    const int tid  = threadIdx.x;
    const int r    = tid >> 2;         // 0..63
    const int q    = tid & 3;          // col group: cols [q*32, q*32+32)

    float acc[32];
    #pragma unroll
    for (int i = 0; i < 32; i++) acc[i] = 0.f;

    for (int kt = 0; kt < 32; kt++) {
        for (int i = tid; i < 64 * 32; i += 256) {
            int rr = i >> 5, kk = i & 31;
            s[rr][kk] = d_S[(size_t)(row0 + rr) * HDIM + kt * 32 + kk];
        }
        for (int i = tid; i < 32 * 128; i += 256) {
            int kk = i >> 7, cc = i & 127;
            w[kk][cc] = Wd[(size_t)(kt * 32 + kk) * VOC + cc];
        }
        __syncthreads();

        #pragma unroll 4
        for (int kk = 0; kk < 32; kk++) {
            float sv = s[r][kk];
            const float4* wrow = reinterpret_cast<const float4*>(&w[kk][q * 32]);
            #pragma unroll
            for (int c4 = 0; c4 < 8; c4++) {
                float4 wv = wrow[c4];
                acc[c4 * 4 + 0] += sv * wv.x;
                acc[c4 * 4 + 1] += sv * wv.y;
                acc[c4 * 4 + 2] += sv * wv.z;
                acc[c4 * 4 + 3] += sv * wv.w;
            }
        }
        __syncthreads();
    }

    // bias + row softmax (4 threads per row cooperate via shfl: lanes differ in bits 0-1)
    float m = -1e30f;
    #pragma unroll
    for (int c = 0; c < 32; c++) {
        acc[c] += bd[q * 32 + c];
        m = fmaxf(m, acc[c]);
    }
    m = fmaxf(m, __shfl_xor_sync(0xFFFFFFFFu, m, 1));
    m = fmaxf(m, __shfl_xor_sync(0xFFFFFFFFu, m, 2));

    float sum = 0.f;
    #pragma unroll
    for (int c = 0; c < 32; c++) {
        acc[c] = expf(acc[c] - m);
        sum += acc[c];
    }
    sum += __shfl_xor_sync(0xFFFFFFFFu, sum, 1);
    sum += __shfl_xor_sync(0xFFFFFFFFu, sum, 2);
    float inv = 1.0f / sum;

    float* orow = out + (size_t)(row0 + r) * VOC + q * 32;
    #pragma unroll
    for (int c4 = 0; c4 < 8; c4++) {
        float4 v;
        v.x = acc[c4 * 4 + 0] * inv;
        v.y = acc[c4 * 4 + 1] * inv;
        v.z = acc[c4 * 4 + 2] * inv;
        v.w = acc[c4 * 4 + 3] * inv;
        reinterpret_cast<float4*>(orow)[c4] = v;
    }
}

// ---------------- launcher ----------------
extern "C" void kernel_launch(void* const* d_in, const int* in_sizes, int n_in,
                              void* d_out, int out_size) {
    (void)in_sizes; (void)n_in; (void)out_size;
    const int*   tokens = (const int*)  d_in[0];
    const float* emb    = (const float*)d_in[1];
    const float* W      = (const float*)d_in[2];
    const float* U      = (const float*)d_in[3];
    const float* b      = (const float*)d_in[4];
    const float* Wd     = (const float*)d_in[5];
    const float* bd     = (const float*)d_in[6];
    float* out = (float*)d_out;

    prep_embW<<<128, 256>>>(emb, W, b);
    prep_U<<<dim3(128, 32), 256>>>(U);
    init_state<<<512, 256>>>();
    for (int t = 0; t < TSEQ; t++)
        lstm_step<<<128, 256>>>(tokens, t);
    decode_kernel<<<1024, 256>>>(Wd, bd, out);
}

// round 6
// speedup vs baseline: 1.6000x; 1.6000x over previous
#include <cuda_runtime.h>
#include <cuda_fp16.h>
#include <cstdint>
#include <cstddef>

#define TSEQ 512
#define BATCH 128
#define HDIM 1024
#define NZ 4096
#define VOC 128
#define EDIM 256

// ---------------- static device buffers ----------------
__device__ half  d_U16[(size_t)NZ * HDIM];            // U^T fp16 [n][k], 8 MB
__device__ float d_embW[VOC * NZ];                    // emb@W + b  [v][n], 2 MB
__device__ half  d_A16[2][BATCH * HDIM];              // ping-pong h (fp16)
__device__ float d_c[BATCH * HDIM];
__device__ float d_h[BATCH * HDIM];
__device__ float d_S[(size_t)BATCH * TSEQ * HDIM];    // fp32 states, 256 MB

// ---------------- PTX helpers ----------------
__device__ __forceinline__ unsigned smaddr(const void* p) {
    return (unsigned)__cvta_generic_to_shared(p);
}
__device__ __forceinline__ void cpa16(void* dst, const void* src) {
    asm volatile("cp.async.cg.shared.global [%0], [%1], 16;\n"
                 :: "r"(smaddr(dst)), "l"(src));
}
__device__ __forceinline__ void ldsm_x4(unsigned* r, const void* p) {
    unsigned a = smaddr(p);
    asm volatile("ldmatrix.sync.aligned.m8n8.x4.shared.b16 {%0,%1,%2,%3}, [%4];\n"
                 : "=r"(r[0]), "=r"(r[1]), "=r"(r[2]), "=r"(r[3]) : "r"(a));
}
__device__ __forceinline__ void ldsm_x2(unsigned* r, const void* p) {
    unsigned a = smaddr(p);
    asm volatile("ldmatrix.sync.aligned.m8n8.x2.shared.b16 {%0,%1}, [%2];\n"
                 : "=r"(r[0]), "=r"(r[1]) : "r"(a));
}
__device__ __forceinline__ void mma16816(float* d, const unsigned* a, const unsigned* b) {
    asm volatile("mma.sync.aligned.m16n8k16.row.col.f32.f16.f16.f32 "
                 "{%0,%1,%2,%3},{%4,%5,%6,%7},{%8,%9},{%0,%1,%2,%3};\n"
                 : "+f"(d[0]), "+f"(d[1]), "+f"(d[2]), "+f"(d[3])
                 : "r"(a[0]), "r"(a[1]), "r"(a[2]), "r"(a[3]),
                   "r"(b[0]), "r"(b[1]));
}
__device__ __forceinline__ float sigmoidf_acc(float x) {
    return 1.0f / (1.0f + expf(-x));
}

// ---------------- prep: embW = emb @ W + b   (128 x 4096, K=256) ----------------
__global__ void __launch_bounds__(256) prep_embW(const float* __restrict__ emb,
                                                 const float* __restrict__ W,
                                                 const float* __restrict__ bias) {
    __shared__ float Ws[EDIM][32];
    const int n0 = blockIdx.x * 32;
    for (int i = threadIdx.x; i < EDIM * 32; i += 256) {
        int e = i >> 5, c = i & 31;
        Ws[e][c] = W[(size_t)e * NZ + n0 + c];
    }
    __syncthreads();
    const int c = threadIdx.x & 31;
    for (int v = threadIdx.x >> 5; v < VOC; v += 8) {
        float a = bias[n0 + c];
        const float* er = emb + v * EDIM;
        #pragma unroll 8
        for (int e = 0; e < EDIM; e++) a += er[e] * Ws[e][c];
        d_embW[v * NZ + n0 + c] = a;
    }
}

// ---------------- prep: U fp32 [k][n] -> d_U16 fp16 [n][k] ----------------
__global__ void __launch_bounds__(256) prep_U(const float* __restrict__ U) {
    __shared__ float tile[32][33];
    const int n0 = blockIdx.x * 32;
    const int k0 = blockIdx.y * 32;
    const int tx = threadIdx.x & 31, ty = threadIdx.x >> 5;
    #pragma unroll
    for (int i = 0; i < 4; i++) {
        int r = ty + i * 8;
        tile[r][tx] = U[(size_t)(k0 + r) * NZ + n0 + tx];
    }
    __syncthreads();
    #pragma unroll
    for (int i = 0; i < 4; i++) {
        int r = ty + i * 8;
        d_U16[(size_t)(n0 + r) * HDIM + k0 + tx] = __float2half_rn(tile[tx][r]);
    }
}

__global__ void init_state() {
    int i = blockIdx.x * blockDim.x + threadIdx.x;
    if (i < BATCH * HDIM) {
        d_c[i] = 0.f;
        d_h[i] = 0.f;
        d_A16[0][i] = __float2half_rn(0.f);
    }
}

// ---------------- LSTM step: HMMA, single fp16 pass, K-chunk 64 ----------------
// Block bn owns h-cols [8bn, 8bn+8) => z-cols {g*1024 + 8bn + j}.
// smem: 4 stages x { A[128][72], B[32][72] } halfs.
#define KC 64
#define NCH 16
#define NST 4
#define A_ROWH 72                           // 64 + 8 pad halfs
#define A_ST_H (128 * A_ROWH)               // 9216 halfs = 18432 B
#define B_ST_H (32 * A_ROWH)                //  2304 halfs =  4608 B
#define ST_H   (A_ST_H + B_ST_H)            // 11520 halfs = 23040 B
#define SMEM_TOTAL (NST * ST_H * 2)         // 92160 B

__global__ void __launch_bounds__(256) lstm_step(const int* __restrict__ tokens, int t) {
    extern __shared__ __align__(16) half smh[];
    float (*zb)[40] = reinterpret_cast<float(*)[40]>(smh);   // 20 KB, reused after GEMM

    const int tid  = threadIdx.x;
    const int bn   = blockIdx.x;
    const int rb   = t & 1, wb = rb ^ 1;
    const int lane = tid & 31, wid = tid >> 5;
    const int wm   = wid & 3;     // 4 warps x 32 rows
    const int wn   = wid >> 2;    // 2 warps x 16 cols

    const half* __restrict__ Asrc = d_A16[rb];

    float acc[2][2][4];
    #pragma unroll
    for (int i = 0; i < 2; i++)
        #pragma unroll
        for (int j = 0; j < 2; j++)
            #pragma unroll
            for (int e = 0; e < 4; e++) acc[i][j][e] = 0.f;

    // ldmatrix lane addressing (validated in R2: rel_err 1.4e-6)
    const int aRow = wm * 32 + (lane & 7) + ((lane >> 3) & 1) * 8;
    const int aCol = ((lane >> 4) & 1) * 8;
    const int bRow = wn * 16 + (lane & 7);
    const int bCol = ((lane >> 3) & 1) * 8;

    // one chunk = 64 k: A 1024 + B 256 = 1280 x 16B cp.async over 256 threads
    auto load_chunk = [&](int ch) {
        half* st = smh + (ch & (NST - 1)) * ST_H;
        const int k0 = ch * KC;
        #pragma unroll
        for (int i = tid; i < 1280; i += 256) {
            if (i < 1024) {
                int r = i >> 3, seg = i & 7;
                cpa16(st + r * A_ROWH + seg * 8,
                      Asrc + (size_t)r * HDIM + k0 + seg * 8);
            } else {
                int j = i - 1024, ci = j >> 3, seg = j & 7;
                int gcol = (ci >> 3) * HDIM + bn * 8 + (ci & 7);
                cpa16(st + A_ST_H + ci * A_ROWH + seg * 8,
                      d_U16 + (size_t)gcol * HDIM + k0 + seg * 8);
            }
        }
        asm volatile("cp.async.commit_group;\n");
    };

    load_chunk(0); load_chunk(1); load_chunk(2);

    for (int ch = 0; ch < NCH; ch++) {
        asm volatile("cp.async.wait_group 2;\n");   // stage ch resident
        __syncthreads();                            // publish ch; retire ch-1

        if (ch + 3 < NCH) load_chunk(ch + 3);       // overwrites stage (ch-1)&3
        else asm volatile("cp.async.commit_group;\n");  // dummy: keep group count

        const half* st = smh + (ch & (NST - 1)) * ST_H;
        const half* Bs = st + A_ST_H;
        #pragma unroll
        for (int ks = 0; ks < 4; ks++) {
            unsigned bf0[2], bf1[2];
            ldsm_x2(bf0, Bs + (bRow    ) * A_ROWH + bCol + ks * 16);
            ldsm_x2(bf1, Bs + (bRow + 8) * A_ROWH + bCol + ks * 16);
            unsigned af0[4], af1[4];
            ldsm_x4(af0, st + (aRow     ) * A_ROWH + aCol + ks * 16);
            ldsm_x4(af1, st + (aRow + 16) * A_ROWH + aCol + ks * 16);
            mma16816(acc[0][0], af0, bf0);
            mma16816(acc[0][1], af0, bf1);
            mma16816(acc[1][0], af1, bf0);
            mma16816(acc[1][1], af1, bf1);
        }
    }
    __syncthreads();

    // ---- spill C (z pre-activations) to smem ----
    #pragma unroll
    for (int ti = 0; ti < 2; ti++)
        #pragma unroll
        for (int tj = 0; tj < 2; tj++)
            #pragma unroll
            for (int e = 0; e < 4; e++) {
                int r = wm * 32 + ti * 16 + (lane >> 2) + (e >> 1) * 8;
                int c = wn * 16 + tj * 8 + (lane & 3) * 2 + (e & 1);
                zb[r][c] = acc[ti][tj][e];
            }
    __syncthreads();

    // ---- block-local gate + state update: 128 rows x 8 h-cols ----
    for (int e = tid; e < 1024; e += 256) {
        const int bb  = e >> 3, j = e & 7;
        const int col = bn * 8 + j;
        const int tok = tokens[bb * TSEQ + t];
        const float* ew = d_embW + (size_t)tok * NZ + col;

        float zi = zb[bb][j]      + ew[0];
        float zf = zb[bb][8 + j]  + ew[HDIM];
        float zg = zb[bb][16 + j] + ew[2 * HDIM];
        float zo = zb[bb][24 + j] + ew[3 * HDIM];

        float ig = sigmoidf_acc(zi);
        float fg = sigmoidf_acc(zf);
        float gg = tanhf(zg);
        float og = sigmoidf_acc(zo);

        const int si = bb * HDIM + col;
        float cp = d_c[si];
        float cn = fg * cp + ig * gg;
        float hn = og * tanhf(cn);

        bool msk = (tok != 0);
        float ho = msk ? hn : d_h[si];
        float co = msk ? cn : cp;

        d_c[si] = co;
        d_h[si] = ho;
        d_S[((size_t)bb * TSEQ + t) * HDIM + col] = ho;
        d_A16[wb][si] = __float2half_rn(ho);
    }
}

// ---------------- decode + softmax ----------------
__global__ void __launch_bounds__(256) decode_kernel(const float* __restrict__ Wd,
                                                     const float* __restrict__ bd,
                                                     float* __restrict__ out) {
    __shared__ float s[64][33];
    __shared__ float w[32][128];
    const int row0 = blockIdx.x * 64;
    const int tid  = threadIdx.x;
    const int r    = tid >> 2;
    const int q    = tid & 3;

    float acc[32];
    #pragma unroll
    for (int i = 0; i < 32; i++) acc[i] = 0.f;

    for (int kt = 0; kt < 32; kt++) {
        for (int i = tid; i < 64 * 32; i += 256) {
            int rr = i >> 5, kk = i & 31;
            s[rr][kk] = d_S[(size_t)(row0 + rr) * HDIM + kt * 32 + kk];
        }
        for (int i = tid; i < 32 * 128; i += 256) {
            int kk = i >> 7, cc = i & 127;
            w[kk][cc] = Wd[(size_t)(kt * 32 + kk) * VOC + cc];
        }
        __syncthreads();

        #pragma unroll 4
        for (int kk = 0; kk < 32; kk++) {
            float sv = s[r][kk];
            const float4* wrow = reinterpret_cast<const float4*>(&w[kk][q * 32]);
            #pragma unroll
            for (int c4 = 0; c4 < 8; c4++) {
                float4 wv = wrow[c4];
                acc[c4 * 4 + 0] += sv * wv.x;
                acc[c4 * 4 + 1] += sv * wv.y;
                acc[c4 * 4 + 2] += sv * wv.z;
                acc[c4 * 4 + 3] += sv * wv.w;
            }
        }
        __syncthreads();
    }

    float m = -1e30f;
    #pragma unroll
    for (int c = 0; c < 32; c++) {
        acc[c] += bd[q * 32 + c];
        m = fmaxf(m, acc[c]);
    }
    m = fmaxf(m, __shfl_xor_sync(0xFFFFFFFFu, m, 1));
    m = fmaxf(m, __shfl_xor_sync(0xFFFFFFFFu, m, 2));

    float sum = 0.f;
    #pragma unroll
    for (int c = 0; c < 32; c++) {
        acc[c] = expf(acc[c] - m);
        sum += acc[c];
    }
    sum += __shfl_xor_sync(0xFFFFFFFFu, sum, 1);
    sum += __shfl_xor_sync(0xFFFFFFFFu, sum, 2);
    float inv = 1.0f / sum;

    float* orow = out + (size_t)(row0 + r) * VOC + q * 32;
    #pragma unroll
    for (int c4 = 0; c4 < 8; c4++) {
        float4 v;
        v.x = acc[c4 * 4 + 0] * inv;
        v.y = acc[c4 * 4 + 1] * inv;
        v.z = acc[c4 * 4 + 2] * inv;
        v.w = acc[c4 * 4 + 3] * inv;
        reinterpret_cast<float4*>(orow)[c4] = v;
    }
}

// ---------------- launcher ----------------
extern "C" void kernel_launch(void* const* d_in, const int* in_sizes, int n_in,
                              void* d_out, int out_size) {
    (void)in_sizes; (void)n_in; (void)out_size;
    const int*   tokens = (const int*)  d_in[0];
    const float* emb    = (const float*)d_in[1];
    const float* W      = (const float*)d_in[2];
    const float* U      = (const float*)d_in[3];
    const float* b      = (const float*)d_in[4];
    const float* Wd     = (const float*)d_in[5];
    const float* bd     = (const float*)d_in[6];
    float* out = (float*)d_out;

    cudaFuncSetAttribute(lstm_step, cudaFuncAttributeMaxDynamicSharedMemorySize,
                         SMEM_TOTAL);

    prep_embW<<<128, 256>>>(emb, W, b);
    prep_U<<<dim3(128, 32), 256>>>(U);
    init_state<<<512, 256>>>();
    for (int t = 0; t < TSEQ; t++)
        lstm_step<<<128, 256, SMEM_TOTAL>>>(tokens, t);
    decode_kernel<<<1024, 256>>>(Wd, bd, out);
}

// round 7
// speedup vs baseline: 1.6339x; 1.0212x over previous
#include <cuda_runtime.h>
#include <cuda_fp16.h>
#include <cstdint>
#include <cstddef>

#define TSEQ 512
#define BATCH 128
#define HDIM 1024
#define NZ 4096
#define VOC 128
#define EDIM 256

// ---------------- static device buffers ----------------
__device__ half  d_U16[(size_t)NZ * HDIM];            // U^T fp16 [n][k], 8 MB
__device__ float d_embW[VOC * NZ];                    // emb@W + b  [v][n], 2 MB
__device__ half  d_A16[2][BATCH * HDIM];              // ping-pong h (fp16)
__device__ float d_c[BATCH * HDIM];
__device__ float d_h[BATCH * HDIM];
__device__ float d_S[(size_t)BATCH * TSEQ * HDIM];    // fp32 states, 256 MB

// ---------------- PTX helpers ----------------
__device__ __forceinline__ unsigned smaddr(const void* p) {
    return (unsigned)__cvta_generic_to_shared(p);
}
__device__ __forceinline__ void cpa16(void* dst, const void* src) {
    asm volatile("cp.async.cg.shared.global [%0], [%1], 16;\n"
                 :: "r"(smaddr(dst)), "l"(src));
}
__device__ __forceinline__ void ldsm_x4(unsigned* r, const void* p) {
    unsigned a = smaddr(p);
    asm volatile("ldmatrix.sync.aligned.m8n8.x4.shared.b16 {%0,%1,%2,%3}, [%4];\n"
                 : "=r"(r[0]), "=r"(r[1]), "=r"(r[2]), "=r"(r[3]) : "r"(a));
}
__device__ __forceinline__ void ldsm_x2(unsigned* r, const void* p) {
    unsigned a = smaddr(p);
    asm volatile("ldmatrix.sync.aligned.m8n8.x2.shared.b16 {%0,%1}, [%2];\n"
                 : "=r"(r[0]), "=r"(r[1]) : "r"(a));
}
__device__ __forceinline__ void mma16816(float* d, const unsigned* a, const unsigned* b) {
    asm volatile("mma.sync.aligned.m16n8k16.row.col.f32.f16.f16.f32 "
                 "{%0,%1,%2,%3},{%4,%5,%6,%7},{%8,%9},{%0,%1,%2,%3};\n"
                 : "+f"(d[0]), "+f"(d[1]), "+f"(d[2]), "+f"(d[3])
                 : "r"(a[0]), "r"(a[1]), "r"(a[2]), "r"(a[3]),
                   "r"(b[0]), "r"(b[1]));
}
__device__ __forceinline__ float sigmoidf_acc(float x) {
    return 1.0f / (1.0f + expf(-x));
}

// ---------------- prep: embW = emb @ W + b   (128 x 4096, K=256) ----------------
__global__ void __launch_bounds__(256) prep_embW(const float* __restrict__ emb,
                                                 const float* __restrict__ W,
                                                 const float* __restrict__ bias) {
    __shared__ float Ws[EDIM][32];
    const int n0 = blockIdx.x * 32;
    for (int i = threadIdx.x; i < EDIM * 32; i += 256) {
        int e = i >> 5, c = i & 31;
        Ws[e][c] = W[(size_t)e * NZ + n0 + c];
    }
    __syncthreads();
    const int c = threadIdx.x & 31;
    for (int v = threadIdx.x >> 5; v < VOC; v += 8) {
        float a = bias[n0 + c];
        const float* er = emb + v * EDIM;
        #pragma unroll 8
        for (int e = 0; e < EDIM; e++) a += er[e] * Ws[e][c];
        d_embW[v * NZ + n0 + c] = a;
    }
}

// ---------------- prep: U fp32 [k][n] -> d_U16 fp16 [n][k] ----------------
__global__ void __launch_bounds__(256) prep_U(const float* __restrict__ U) {
    __shared__ float tile[32][33];
    const int n0 = blockIdx.x * 32;
    const int k0 = blockIdx.y * 32;
    const int tx = threadIdx.x & 31, ty = threadIdx.x >> 5;
    #pragma unroll
    for (int i = 0; i < 4; i++) {
        int r = ty + i * 8;
        tile[r][tx] = U[(size_t)(k0 + r) * NZ + n0 + tx];
    }
    __syncthreads();
    #pragma unroll
    for (int i = 0; i < 4; i++) {
        int r = ty + i * 8;
        d_U16[(size_t)(n0 + r) * HDIM + k0 + tx] = __float2half_rn(tile[tx][r]);
    }
}

__global__ void init_state() {
    int i = blockIdx.x * blockDim.x + threadIdx.x;
    if (i < BATCH * HDIM) {
        d_c[i] = 0.f;
        d_h[i] = 0.f;
        d_A16[0][i] = __float2half_rn(0.f);
    }
}

// ---------------- LSTM step ----------------
// Block bn owns h-cols [8bn, 8bn+8) => z-cols {g*1024 + 8bn + j}.
// B (U cols, 32 x 1024 halfs) fully preloaded once. A pipelined per warp-PAIR
// (warps wid, wid+4 share wm): 4-stage ring, named-barrier sync only.
#define KC 64
#define NCH 16
#define B_ROWH 1032                           // 1024 + 8 pad halfs
#define B_H    (32 * B_ROWH)                  // 33024 halfs = 66048 B
#define A_STG_H (32 * 72)                     // 2304 halfs = 4608 B per stage
#define SMEM_TOTAL (B_H * 2 + 4 * 4 * A_STG_H * 2)   // 66048 + 73728 = 139776 B

__global__ void __launch_bounds__(256) lstm_step(const int* __restrict__ tokens, int t) {
    extern __shared__ __align__(16) half smh[];
    float (*zb)[40] = reinterpret_cast<float(*)[40]>(smh);   // 20 KB, overlaps B (dead)

    const int tid  = threadIdx.x;
    const int bn   = blockIdx.x;
    const int rb   = t & 1, wb = rb ^ 1;
    const int lane = tid & 31, wid = tid >> 5;
    const int wm   = wid & 3;     // pair id: warps {wm, wm+4} share A rows
    const int wn   = wid >> 2;    // 0/1: N-half, also selects A-row half to load

    const half* __restrict__ Asrc = d_A16[rb];
    half* Bs    = smh;                                  // B[32][1032]
    half* Apair = smh + B_H + wm * 4 * A_STG_H;         // 4 stages x [32][72]

    // ---- B preload: whole 32x1024 strip, 16 cpa16/thread, group 0 ----
    #pragma unroll
    for (int w = 0; w < 16; w++) {
        int i = tid + w * 256;            // 0..4095
        int ci = i >> 7, seg = i & 127;
        int gcol = (ci >> 3) * HDIM + bn * 8 + (ci & 7);
        cpa16(Bs + ci * B_ROWH + seg * 8, d_U16 + (size_t)gcol * HDIM + seg * 8);
    }
    asm volatile("cp.async.commit_group;\n");

    // ---- per-warp A loader: 16 rows (own half of pair's 32) x 64 k ----
    auto load_A = [&](int ch) {
        half* st = Apair + (ch & 3) * A_STG_H;
        const int k0 = ch * KC;
        #pragma unroll
        for (int w = 0; w < 4; w++) {
            int i = lane + w * 32;                    // 0..127
            int lr = wn * 16 + (i >> 3), seg = i & 7; // local row, 16B seg
            cpa16(st + lr * 72 + seg * 8,
                  Asrc + (size_t)(wm * 32 + lr) * HDIM + k0 + seg * 8);
        }
        asm volatile("cp.async.commit_group;\n");
    };
    load_A(0); load_A(1); load_A(2);

    float acc[2][2][4];
    #pragma unroll
    for (int i = 0; i < 2; i++)
        #pragma unroll
        for (int j = 0; j < 2; j++)
            #pragma unroll
            for (int e = 0; e < 4; e++) acc[i][j][e] = 0.f;

    const int aRowL = (lane & 7) + ((lane >> 3) & 1) * 8;
    const int aCol  = ((lane >> 4) & 1) * 8;
    const int bRow  = wn * 16 + (lane & 7);
    const int bCol  = ((lane >> 3) & 1) * 8;
    const int barid = wm + 1;

    for (int ch = 0; ch < NCH; ch++) {
        asm volatile("cp.async.wait_group 2;\n");       // own B(+ch==0) / A_ch done
        if (ch == 0) __syncthreads();                   // publish B + pair A0
        else asm volatile("bar.sync %0, 64;\n" :: "r"(barid));  // pair-only sync

        const half* st = Apair + (ch & 3) * A_STG_H;
        const half* Bc = Bs + ch * KC;
        #pragma unroll
        for (int ks = 0; ks < 4; ks++) {
            unsigned bf0[2], bf1[2];
            ldsm_x2(bf0, Bc + (bRow    ) * B_ROWH + bCol + ks * 16);
            ldsm_x2(bf1, Bc + (bRow + 8) * B_ROWH + bCol + ks * 16);
            unsigned af0[4], af1[4];
            ldsm_x4(af0, st + (aRowL     ) * 72 + aCol + ks * 16);
            ldsm_x4(af1, st + (aRowL + 16) * 72 + aCol + ks * 16);
            mma16816(acc[0][0], af0, bf0);
            mma16816(acc[0][1], af0, bf1);
            mma16816(acc[1][0], af1, bf0);
            mma16816(acc[1][1], af1, bf1);
        }

        if (ch + 3 < NCH) load_A(ch + 3);               // stage (ch-1)&3: pair done with it
        else asm volatile("cp.async.commit_group;\n");  // dummy: keep group arithmetic
    }
    __syncthreads();

    // ---- spill C (z pre-activations) to smem (overlaps dead B region) ----
    #pragma unroll
    for (int ti = 0; ti < 2; ti++)
        #pragma unroll
        for (int tj = 0; tj < 2; tj++)
            #pragma unroll
            for (int e = 0; e < 4; e++) {
                int r = wm * 32 + ti * 16 + (lane >> 2) + (e >> 1) * 8;
                int c = wn * 16 + tj * 8 + (lane & 3) * 2 + (e & 1);
                zb[r][c] = acc[ti][tj][e];
            }
    __syncthreads();

    // ---- block-local gate + state update: 128 rows x 8 h-cols ----
    for (int e = tid; e < 1024; e += 256) {
        const int bb  = e >> 3, j = e & 7;
        const int col = bn * 8 + j;
        const int tok = tokens[bb * TSEQ + t];
        const float* ew = d_embW + (size_t)tok * NZ + col;

        float zi = zb[bb][j]      + ew[0];
        float zf = zb[bb][8 + j]  + ew[HDIM];
        float zg = zb[bb][16 + j] + ew[2 * HDIM];
        float zo = zb[bb][24 + j] + ew[3 * HDIM];

        float ig = sigmoidf_acc(zi);
        float fg = sigmoidf_acc(zf);
        float gg = tanhf(zg);
        float og = sigmoidf_acc(zo);

        const int si = bb * HDIM + col;
        float cp = d_c[si];
        float cn = fg * cp + ig * gg;
        float hn = og * tanhf(cn);

        bool msk = (tok != 0);
        float ho = msk ? hn : d_h[si];
        float co = msk ? cn : cp;

        d_c[si] = co;
        d_h[si] = ho;
        d_S[((size_t)bb * TSEQ + t) * HDIM + col] = ho;
        d_A16[wb][si] = __float2half_rn(ho);
    }
}

// ---------------- decode + softmax ----------------
__global__ void __launch_bounds__(256) decode_kernel(const float* __restrict__ Wd,
                                                     const float* __restrict__ bd,
                                                     float* __restrict__ out) {
    __shared__ float s[64][33];
    __shared__ float w[32][128];
    const int row0 = blockIdx.x * 64;
    const int tid  = threadIdx.x;
    const int r    = tid >> 2;
    const int q    = tid & 3;

    float acc[32];
    #pragma unroll
    for (int i = 0; i < 32; i++) acc[i] = 0.f;

    for (int kt = 0; kt < 32; kt++) {
        for (int i = tid; i < 64 * 32; i += 256) {
            int rr = i >> 5, kk = i & 31;
            s[rr][kk] = d_S[(size_t)(row0 + rr) * HDIM + kt * 32 + kk];
        }
        for (int i = tid; i < 32 * 128; i += 256) {
            int kk = i >> 7, cc = i & 127;
            w[kk][cc] = Wd[(size_t)(kt * 32 + kk) * VOC + cc];
        }
        __syncthreads();

        #pragma unroll 4
        for (int kk = 0; kk < 32; kk++) {
            float sv = s[r][kk];
            const float4* wrow = reinterpret_cast<const float4*>(&w[kk][q * 32]);
            #pragma unroll
            for (int c4 = 0; c4 < 8; c4++) {
                float4 wv = wrow[c4];
                acc[c4 * 4 + 0] += sv * wv.x;
                acc[c4 * 4 + 1] += sv * wv.y;
                acc[c4 * 4 + 2] += sv * wv.z;
                acc[c4 * 4 + 3] += sv * wv.w;
            }
        }
        __syncthreads();
    }

    float m = -1e30f;
    #pragma unroll
    for (int c = 0; c < 32; c++) {
        acc[c] += bd[q * 32 + c];
        m = fmaxf(m, acc[c]);
    }
    m = fmaxf(m, __shfl_xor_sync(0xFFFFFFFFu, m, 1));
    m = fmaxf(m, __shfl_xor_sync(0xFFFFFFFFu, m, 2));

    float sum = 0.f;
    #pragma unroll
    for (int c = 0; c < 32; c++) {
        acc[c] = expf(acc[c] - m);
        sum += acc[c];
    }
    sum += __shfl_xor_sync(0xFFFFFFFFu, sum, 1);
    sum += __shfl_xor_sync(0xFFFFFFFFu, sum, 2);
    float inv = 1.0f / sum;

    float* orow = out + (size_t)(row0 + r) * VOC + q * 32;
    #pragma unroll
    for (int c4 = 0; c4 < 8; c4++) {
        float4 v;
        v.x = acc[c4 * 4 + 0] * inv;
        v.y = acc[c4 * 4 + 1] * inv;
        v.z = acc[c4 * 4 + 2] * inv;
        v.w = acc[c4 * 4 + 3] * inv;
        reinterpret_cast<float4*>(orow)[c4] = v;
    }
}

// ---------------- launcher ----------------
extern "C" void kernel_launch(void* const* d_in, const int* in_sizes, int n_in,
                              void* d_out, int out_size) {
    (void)in_sizes; (void)n_in; (void)out_size;
    const int*   tokens = (const int*)  d_in[0];
    const float* emb    = (const float*)d_in[1];
    const float* W      = (const float*)d_in[2];
    const float* U      = (const float*)d_in[3];
    const float* b      = (const float*)d_in[4];
    const float* Wd     = (const float*)d_in[5];
    const float* bd     = (const float*)d_in[6];
    float* out = (float*)d_out;

    cudaFuncSetAttribute(lstm_step, cudaFuncAttributeMaxDynamicSharedMemorySize,
                         SMEM_TOTAL);

    prep_embW<<<128, 256>>>(emb, W, b);
    prep_U<<<dim3(128, 32), 256>>>(U);
    init_state<<<512, 256>>>();
    for (int t = 0; t < TSEQ; t++)
        lstm_step<<<128, 256, SMEM_TOTAL>>>(tokens, t);
    decode_kernel<<<1024, 256>>>(Wd, bd, out);
}

// round 8
// speedup vs baseline: 1.7883x; 1.0945x over previous
#include <cuda_runtime.h>
#include <cuda_fp16.h>
#include <cstdint>
#include <cstddef>

#define TSEQ 512
#define BATCH 128
#define HDIM 1024
#define NZ 4096
#define VOC 128
#define EDIM 256
#define NBLK 128

// ---------------- static device buffers ----------------
__device__ half  d_U16[(size_t)NZ * HDIM];            // U^T fp16 [n][k], 8 MB
__device__ float d_embW[VOC * NZ];                    // emb@W + b  [v][n], 2 MB
__device__ half  d_A16[2][BATCH * HDIM];              // ping-pong h (fp16)
__device__ float d_c[BATCH * HDIM];
__device__ float d_h[BATCH * HDIM];
__device__ float d_S[(size_t)BATCH * TSEQ * HDIM];    // fp32 states, 256 MB
__device__ unsigned g_cnt;                            // grid barrier state
__device__ unsigned g_gen;

// ---------------- PTX helpers ----------------
__device__ __forceinline__ unsigned smaddr(const void* p) {
    return (unsigned)__cvta_generic_to_shared(p);
}
__device__ __forceinline__ void cpa16(void* dst, const void* src) {
    asm volatile("cp.async.cg.shared.global [%0], [%1], 16;\n"
                 :: "r"(smaddr(dst)), "l"(src));
}
__device__ __forceinline__ void ldsm_x4(unsigned* r, const void* p) {
    unsigned a = smaddr(p);
    asm volatile("ldmatrix.sync.aligned.m8n8.x4.shared.b16 {%0,%1,%2,%3}, [%4];\n"
                 : "=r"(r[0]), "=r"(r[1]), "=r"(r[2]), "=r"(r[3]) : "r"(a));
}
__device__ __forceinline__ void ldsm_x2(unsigned* r, const void* p) {
    unsigned a = smaddr(p);
    asm volatile("ldmatrix.sync.aligned.m8n8.x2.shared.b16 {%0,%1}, [%2];\n"
                 : "=r"(r[0]), "=r"(r[1]) : "r"(a));
}
__device__ __forceinline__ void mma16816(float* d, const unsigned* a, const unsigned* b) {
    asm volatile("mma.sync.aligned.m16n8k16.row.col.f32.f16.f16.f32 "
                 "{%0,%1,%2,%3},{%4,%5,%6,%7},{%8,%9},{%0,%1,%2,%3};\n"
                 : "+f"(d[0]), "+f"(d[1]), "+f"(d[2]), "+f"(d[3])
                 : "r"(a[0]), "r"(a[1]), "r"(a[2]), "r"(a[3]),
                   "r"(b[0]), "r"(b[1]));
}
__device__ __forceinline__ float sigmoidf_acc(float x) {
    return 1.0f / (1.0f + expf(-x));
}

// ---------------- prep: embW = emb @ W + b   (128 x 4096, K=256) ----------------
__global__ void __launch_bounds__(256) prep_embW(const float* __restrict__ emb,
                                                 const float* __restrict__ W,
                                                 const float* __restrict__ bias) {
    __shared__ float Ws[EDIM][32];
    const int n0 = blockIdx.x * 32;
    for (int i = threadIdx.x; i < EDIM * 32; i += 256) {
        int e = i >> 5, c = i & 31;
        Ws[e][c] = W[(size_t)e * NZ + n0 + c];
    }
    __syncthreads();
    const int c = threadIdx.x & 31;
    for (int v = threadIdx.x >> 5; v < VOC; v += 8) {
        float a = bias[n0 + c];
        const float* er = emb + v * EDIM;
        #pragma unroll 8
        for (int e = 0; e < EDIM; e++) a += er[e] * Ws[e][c];
        d_embW[v * NZ + n0 + c] = a;
    }
}

// ---------------- prep: U fp32 [k][n] -> d_U16 fp16 [n][k] ----------------
__global__ void __launch_bounds__(256) prep_U(const float* __restrict__ U) {
    __shared__ float tile[32][33];
    const int n0 = blockIdx.x * 32;
    const int k0 = blockIdx.y * 32;
    const int tx = threadIdx.x & 31, ty = threadIdx.x >> 5;
    #pragma unroll
    for (int i = 0; i < 4; i++) {
        int r = ty + i * 8;
        tile[r][tx] = U[(size_t)(k0 + r) * NZ + n0 + tx];
    }
    __syncthreads();
    #pragma unroll
    for (int i = 0; i < 4; i++) {
        int r = ty + i * 8;
        d_U16[(size_t)(n0 + r) * HDIM + k0 + tx] = __float2half_rn(tile[tx][r]);
    }
}

__global__ void init_state() {
    int i = blockIdx.x * blockDim.x + threadIdx.x;
    if (i < BATCH * HDIM) {
        d_c[i] = 0.f;
        d_h[i] = 0.f;
        d_A16[0][i] = __float2half_rn(0.f);
    }
}

// ---------------- persistent LSTM: all 512 steps in one kernel ----------------
// Block bn owns h-cols [8bn, 8bn+8) => z-cols {g*1024 + 8bn + j}.
// 512 threads = 16 warps = 8 pairs (wm=wid&7) x 2 (wn=wid>>3). Pair owns 16 A-rows.
// B (32 x 1024 halfs) resident in smem for the entire sequence.
#define KC 64
#define NCH 16
#define NST 6
#define B_ROWH 1032                            // 1024 + 8 pad halfs
#define B_H    (32 * B_ROWH)                   // 33024 halfs = 66048 B
#define A_STG_H (16 * 72)                      // 1152 halfs = 2304 B per stage
#define SMEM_TOTAL ((B_H + 8 * NST * A_STG_H) * 2)   // 66048 + 110592 = 176640 B

__global__ void __launch_bounds__(512) lstm_persist(const int* __restrict__ tokens) {
    extern __shared__ __align__(16) half smh[];
    half* Bs = smh;                                       // B[32][1032]
    float (*zb)[40] = reinterpret_cast<float(*)[40]>(smh + B_H);  // overlaps A stages

    const int tid  = threadIdx.x;
    const int bn   = blockIdx.x;
    const int lane = tid & 31, wid = tid >> 5;
    const int wm   = wid & 7;      // pair id: warps {wm, wm+8}, 16 A-rows
    const int wn   = wid >> 3;     // N-half (16 cols), also A-load half

    half* Apair = smh + B_H + wm * (NST * A_STG_H);

    unsigned gen = 0;
    if (tid == 0) gen = *(volatile unsigned*)&g_gen;

    // ---- B preload ONCE: 32 x 1024 strip, 8 cpa16/thread ----
    #pragma unroll
    for (int w = 0; w < 8; w++) {
        int i = tid + w * 512;                 // 0..4095
        int ci = i >> 7, seg = i & 127;
        int gcol = (ci >> 3) * HDIM + bn * 8 + (ci & 7);
        cpa16(Bs + ci * B_ROWH + seg * 8, d_U16 + (size_t)gcol * HDIM + seg * 8);
    }
    asm volatile("cp.async.commit_group;\ncp.async.wait_group 0;\n");
    __syncthreads();

    const int aRowL = (lane & 7) + ((lane >> 3) & 1) * 8;
    const int aCol  = ((lane >> 4) & 1) * 8;
    const int bRow  = wn * 16 + (lane & 7);
    const int bCol  = ((lane >> 3) & 1) * 8;
    const int barid = wm + 1;

    for (int t = 0; t < TSEQ; t++) {
        const int rb = t & 1, wb = rb ^ 1;
        const half* __restrict__ Asrc = d_A16[rb];

        // per-warp A loader: own half (8 rows) of pair's 16 rows x 64 k
        auto load_A = [&](int ch) {
            half* st = Apair + (ch % NST) * A_STG_H;
            const int k0 = ch * KC;
            #pragma unroll
            for (int w = 0; w < 2; w++) {
                int i = wn * 64 + w * 32 + lane;          // [wn*64, wn*64+64)
                int lr = i >> 3, seg = i & 7;             // lr 0..15
                cpa16(st + lr * 72 + seg * 8,
                      Asrc + (size_t)(wm * 16 + lr) * HDIM + k0 + seg * 8);
            }
            asm volatile("cp.async.commit_group;\n");
        };
        load_A(0); load_A(1); load_A(2); load_A(3); load_A(4);

        float acc[2][4];
        #pragma unroll
        for (int j = 0; j < 2; j++)
            #pragma unroll
            for (int e = 0; e < 4; e++) acc[j][e] = 0.f;

        for (int ch = 0; ch < NCH; ch++) {
            asm volatile("cp.async.wait_group 4;\n");            // own chunk ch done
            asm volatile("bar.sync %0, 64;\n" :: "r"(barid));    // partner's too

            const half* st = Apair + (ch % NST) * A_STG_H;
            const half* Bc = Bs + ch * KC;
            #pragma unroll
            for (int ks = 0; ks < 4; ks++) {
                unsigned bf0[2], bf1[2];
                ldsm_x2(bf0, Bc + (bRow    ) * B_ROWH + bCol + ks * 16);
                ldsm_x2(bf1, Bc + (bRow + 8) * B_ROWH + bCol + ks * 16);
                unsigned af[4];
                ldsm_x4(af, st + aRowL * 72 + aCol + ks * 16);
                mma16816(acc[0], af, bf0);
                mma16816(acc[1], af, bf1);
            }

            if (ch + 5 < NCH) load_A(ch + 5);
            else asm volatile("cp.async.commit_group;\n");       // keep group count
        }
        __syncthreads();                                          // all GEMM reads done

        // ---- spill z to smem (overlaps now-dead A stages) ----
        #pragma unroll
        for (int tj = 0; tj < 2; tj++)
            #pragma unroll
            for (int e = 0; e < 4; e++) {
                int r = wm * 16 + (lane >> 2) + (e >> 1) * 8;
                int c = wn * 16 + tj * 8 + (lane & 3) * 2 + (e & 1);
                zb[r][c] = acc[tj][e];
            }
        __syncthreads();

        // ---- gate + state update: 2 elements/thread ----
        #pragma unroll
        for (int rep = 0; rep < 2; rep++) {
            const int e   = tid + rep * 512;
            const int bb  = e >> 3, j = e & 7;
            const int col = bn * 8 + j;
            const int tok = tokens[bb * TSEQ + t];
            const float* ew = d_embW + (size_t)tok * NZ + col;

            float zi = zb[bb][j]      + ew[0];
            float zf = zb[bb][8 + j]  + ew[HDIM];
            float zg = zb[bb][16 + j] + ew[2 * HDIM];
            float zo = zb[bb][24 + j] + ew[3 * HDIM];

            float ig = sigmoidf_acc(zi);
            float fg = sigmoidf_acc(zf);
            float gg = tanhf(zg);
            float og = sigmoidf_acc(zo);

            const int si = bb * HDIM + col;
            float cp = d_c[si];
            float cn = fg * cp + ig * gg;
            float hn = og * tanhf(cn);

            bool msk = (tok != 0);
            float ho = msk ? hn : d_h[si];
            float co = msk ? cn : cp;

            d_c[si] = co;
            d_h[si] = ho;
            d_S[((size_t)bb * TSEQ + t) * HDIM + col] = ho;
            d_A16[wb][si] = __float2half_rn(ho);
        }

        // ---- grid barrier: h(t) published to all blocks ----
        __threadfence();
        __syncthreads();
        if (tid == 0) {
            unsigned arr = atomicAdd(&g_cnt, 1);
            if (arr == NBLK - 1) {
                g_cnt = 0;
                __threadfence();
                atomicExch(&g_gen, gen + 1);
            } else {
                while (*(volatile unsigned*)&g_gen != gen + 1) { }
            }
            __threadfence();
        }
        __syncthreads();
        gen++;
    }
}

// ---------------- decode + softmax ----------------
__global__ void __launch_bounds__(256) decode_kernel(const float* __restrict__ Wd,
                                                     const float* __restrict__ bd,
                                                     float* __restrict__ out) {
    __shared__ float s[64][33];
    __shared__ float w[32][128];
    const int row0 = blockIdx.x * 64;
    const int tid  = threadIdx.x;
    const int r    = tid >> 2;
    const int q    = tid & 3;

    float acc[32];
    #pragma unroll
    for (int i = 0; i < 32; i++) acc[i] = 0.f;

    for (int kt = 0; kt < 32; kt++) {
        for (int i = tid; i < 64 * 32; i += 256) {
            int rr = i >> 5, kk = i & 31;
            s[rr][kk] = d_S[(size_t)(row0 + rr) * HDIM + kt * 32 + kk];
        }
        for (int i = tid; i < 32 * 128; i += 256) {
            int kk = i >> 7, cc = i & 127;
            w[kk][cc] = Wd[(size_t)(kt * 32 + kk) * VOC + cc];
        }
        __syncthreads();

        #pragma unroll 4
        for (int kk = 0; kk < 32; kk++) {
            float sv = s[r][kk];
            const float4* wrow = reinterpret_cast<const float4*>(&w[kk][q * 32]);
            #pragma unroll
            for (int c4 = 0; c4 < 8; c4++) {
                float4 wv = wrow[c4];
                acc[c4 * 4 + 0] += sv * wv.x;
                acc[c4 * 4 + 1] += sv * wv.y;
                acc[c4 * 4 + 2] += sv * wv.z;
                acc[c4 * 4 + 3] += sv * wv.w;
            }
        }
        __syncthreads();
    }

    float m = -1e30f;
    #pragma unroll
    for (int c = 0; c < 32; c++) {
        acc[c] += bd[q * 32 + c];
        m = fmaxf(m, acc[c]);
    }
    m = fmaxf(m, __shfl_xor_sync(0xFFFFFFFFu, m, 1));
    m = fmaxf(m, __shfl_xor_sync(0xFFFFFFFFu, m, 2));

    float sum = 0.f;
    #pragma unroll
    for (int c = 0; c < 32; c++) {
        acc[c] = expf(acc[c] - m);
        sum += acc[c];
    }
    sum += __shfl_xor_sync(0xFFFFFFFFu, sum, 1);
    sum += __shfl_xor_sync(0xFFFFFFFFu, sum, 2);
    float inv = 1.0f / sum;

    float* orow = out + (size_t)(row0 + r) * VOC + q * 32;
    #pragma unroll
    for (int c4 = 0; c4 < 8; c4++) {
        float4 v;
        v.x = acc[c4 * 4 + 0] * inv;
        v.y = acc[c4 * 4 + 1] * inv;
        v.z = acc[c4 * 4 + 2] * inv;
        v.w = acc[c4 * 4 + 3] * inv;
        reinterpret_cast<float4*>(orow)[c4] = v;
    }
}

// ---------------- launcher ----------------
extern "C" void kernel_launch(void* const* d_in, const int* in_sizes, int n_in,
                              void* d_out, int out_size) {
    (void)in_sizes; (void)n_in; (void)out_size;
    const int*   tokens = (const int*)  d_in[0];
    const float* emb    = (const float*)d_in[1];
    const float* W      = (const float*)d_in[2];
    const float* U      = (const float*)d_in[3];
    const float* b      = (const float*)d_in[4];
    const float* Wd     = (const float*)d_in[5];
    const float* bd     = (const float*)d_in[6];
    float* out = (float*)d_out;

    cudaFuncSetAttribute(lstm_persist, cudaFuncAttributeMaxDynamicSharedMemorySize,
                         SMEM_TOTAL);

    prep_embW<<<128, 256>>>(emb, W, b);
    prep_U<<<dim3(128, 32), 256>>>(U);
    init_state<<<512, 256>>>();
    lstm_persist<<<NBLK, 512, SMEM_TOTAL>>>(tokens);
    decode_kernel<<<1024, 256>>>(Wd, bd, out);
}